// round 1
// baseline (speedup 1.0000x reference)
#include <cuda_runtime.h>
#include <math.h>

#define NP 50000
#define NL 10000
#define LL 8
#define DEG 40
#define D 64
#define ITERS 8
#define PW 4   // paths per warp in the path-GRU kernel

// ---------------- device scratch (static allocation: allowed) ----------------
__device__ float g_path_state[NP * D];                 // 12.8 MB
__device__ float g_seq[(size_t)NP * 9 * D];            // 115.2 MB: path_state_sequence
__device__ float g_link_state[NL * D];                 // 2.56 MB

__device__ __forceinline__ float sigmoidf_(float x) { return 1.f / (1.f + expf(-x)); }

// ---------------- path embedding: relu(relu(in@W1+b1)@W2+b2) ----------------
__global__ void k_path_embed(const float* __restrict__ ft, const float* __restrict__ fp,
                             const float* __restrict__ fps,
                             const float* __restrict__ w1, const float* __restrict__ b1,
                             const float* __restrict__ w2, const float* __restrict__ b2) {
    __shared__ float s_w1[3 * D], s_w2[D * D], s_b1[D], s_b2[D];
    for (int i = threadIdx.x; i < 3 * D; i += blockDim.x) s_w1[i] = w1[i];
    for (int i = threadIdx.x; i < D * D; i += blockDim.x) s_w2[i] = w2[i];
    for (int i = threadIdx.x; i < D; i += blockDim.x) { s_b1[i] = b1[i]; s_b2[i] = b2[i]; }
    __syncthreads();
    int gw = (blockIdx.x * blockDim.x + threadIdx.x) >> 5;
    int lane = threadIdx.x & 31;
    if (gw >= NP) return;
    int p = gw;
    float i0 = ft[p] * 1e-4f;
    float i1 = fp[p] * 1e-3f;
    float i2 = fps[p] * 1e-3f;
    float h0 = fmaxf(0.f, i0 * s_w1[lane]      + i1 * s_w1[D + lane]      + i2 * s_w1[2 * D + lane]      + s_b1[lane]);
    float h1 = fmaxf(0.f, i0 * s_w1[32 + lane] + i1 * s_w1[D + 32 + lane] + i2 * s_w1[2 * D + 32 + lane] + s_b1[32 + lane]);
    float o0 = s_b2[lane], o1 = s_b2[32 + lane];
#pragma unroll
    for (int k = 0; k < D; k++) {
        float hk = (k < 32) ? __shfl_sync(0xffffffffu, h0, k) : __shfl_sync(0xffffffffu, h1, k - 32);
        o0 += hk * s_w2[k * D + lane];
        o1 += hk * s_w2[k * D + 32 + lane];
    }
    g_path_state[p * D + lane]      = fmaxf(0.f, o0);
    g_path_state[p * D + 32 + lane] = fmaxf(0.f, o1);
}

// ---------------- link embedding (includes load computation) ----------------
__global__ void k_link_embed(const float* __restrict__ ft, const float* __restrict__ cap,
                             const int* __restrict__ p2l,
                             const float* __restrict__ w1, const float* __restrict__ b1,
                             const float* __restrict__ w2, const float* __restrict__ b2) {
    __shared__ float s_w1[2 * D], s_w2[D * D], s_b1[D], s_b2[D];
    for (int i = threadIdx.x; i < 2 * D; i += blockDim.x) s_w1[i] = w1[i];
    for (int i = threadIdx.x; i < D * D; i += blockDim.x) s_w2[i] = w2[i];
    for (int i = threadIdx.x; i < D; i += blockDim.x) { s_b1[i] = b1[i]; s_b2[i] = b2[i]; }
    __syncthreads();
    int gw = (blockIdx.x * blockDim.x + threadIdx.x) >> 5;
    int lane = threadIdx.x & 31;
    if (gw >= NL) return;
    int l = gw;
    // load = sum_d traffic[p2l[l][d][0]] / (cap * 1e9)
    float s = 0.f;
    for (int d = lane; d < DEG; d += 32) s += ft[p2l[(l * DEG + d) * 2]];
#pragma unroll
    for (int off = 16; off; off >>= 1) s += __shfl_xor_sync(0xffffffffu, s, off);
    float c = cap[l];
    float i0 = c * 1e-5f;
    float i1 = s / (c * 1e9f);
    float h0 = fmaxf(0.f, i0 * s_w1[lane]      + i1 * s_w1[D + lane]      + s_b1[lane]);
    float h1 = fmaxf(0.f, i0 * s_w1[32 + lane] + i1 * s_w1[D + 32 + lane] + s_b1[32 + lane]);
    float o0 = s_b2[lane], o1 = s_b2[32 + lane];
#pragma unroll
    for (int k = 0; k < D; k++) {
        float hk = (k < 32) ? __shfl_sync(0xffffffffu, h0, k) : __shfl_sync(0xffffffffu, h1, k - 32);
        o0 += hk * s_w2[k * D + lane];
        o1 += hk * s_w2[k * D + 32 + lane];
    }
    g_link_state[l * D + lane]      = fmaxf(0.f, o0);
    g_link_state[l * D + 32 + lane] = fmaxf(0.f, o1);
}

// ---------------- path GRU scan over L=8 steps, PW paths per warp ----------------
__global__ void k_path_gru(const int* __restrict__ l2p,
                           const float* __restrict__ wx, const float* __restrict__ wh,
                           const float* __restrict__ bx, const float* __restrict__ bh) {
    extern __shared__ float sm[];
    float* s_wx = sm;                 // D*3D
    float* s_wh = sm + D * 3 * D;     // D*3D
    float* s_bx = sm + 2 * D * 3 * D; // 3D
    float* s_bh = s_bx + 3 * D;       // 3D
    for (int i = threadIdx.x; i < D * 3 * D; i += blockDim.x) { s_wx[i] = wx[i]; s_wh[i] = wh[i]; }
    for (int i = threadIdx.x; i < 3 * D; i += blockDim.x) { s_bx[i] = bx[i]; s_bh[i] = bh[i]; }
    __syncthreads();

    int gw = (blockIdx.x * blockDim.x + threadIdx.x) >> 5;
    int lane = threadIdx.x & 31;
    int p0 = gw * PW;

    float h0[PW], h1[PW];
    bool valid[PW];
    int pidx[PW];
#pragma unroll
    for (int w = 0; w < PW; w++) {
        int p = p0 + w;
        valid[w] = (p < NP);
        pidx[w] = valid[w] ? p : 0;
        h0[w] = g_path_state[pidx[w] * D + lane];
        h1[w] = g_path_state[pidx[w] * D + 32 + lane];
        if (valid[w]) {
            g_seq[((size_t)p * 9 + 0) * D + lane]      = h0[w];
            g_seq[((size_t)p * 9 + 0) * D + 32 + lane] = h1[w];
        }
    }

    for (int t = 0; t < LL; t++) {
        float x0[PW], x1[PW];
#pragma unroll
        for (int w = 0; w < PW; w++) {
            int li = l2p[pidx[w] * LL + t];
            x0[w] = g_link_state[li * D + lane];
            x1[w] = g_link_state[li * D + 32 + lane];
        }
        float mx[PW][6], mh[PW][6];
#pragma unroll
        for (int w = 0; w < PW; w++)
#pragma unroll
            for (int m = 0; m < 6; m++) { mx[w][m] = s_bx[m * 32 + lane]; mh[w][m] = s_bh[m * 32 + lane]; }

#pragma unroll 16
        for (int k = 0; k < D; k++) {
            float wxv[6], whv[6];
#pragma unroll
            for (int m = 0; m < 6; m++) {
                wxv[m] = s_wx[k * 192 + m * 32 + lane];
                whv[m] = s_wh[k * 192 + m * 32 + lane];
            }
#pragma unroll
            for (int w = 0; w < PW; w++) {
                float xk = __shfl_sync(0xffffffffu, (k < 32) ? x0[w] : x1[w], k & 31);
                float hk = __shfl_sync(0xffffffffu, (k < 32) ? h0[w] : h1[w], k & 31);
#pragma unroll
                for (int m = 0; m < 6; m++) {
                    mx[w][m] += xk * wxv[m];
                    mh[w][m] += hk * whv[m];
                }
            }
        }

#pragma unroll
        for (int w = 0; w < PW; w++) {
            float z0 = sigmoidf_(mx[w][0] + mh[w][0]);
            float z1 = sigmoidf_(mx[w][1] + mh[w][1]);
            float r0 = sigmoidf_(mx[w][2] + mh[w][2]);
            float r1 = sigmoidf_(mx[w][3] + mh[w][3]);
            float hh0 = tanhf(mx[w][4] + r0 * mh[w][4]);
            float hh1 = tanhf(mx[w][5] + r1 * mh[w][5]);
            h0[w] = z0 * h0[w] + (1.f - z0) * hh0;
            h1[w] = z1 * h1[w] + (1.f - z1) * hh1;
            if (valid[w]) {
                g_seq[((size_t)(p0 + w) * 9 + t + 1) * D + lane]      = h0[w];
                g_seq[((size_t)(p0 + w) * 9 + t + 1) * D + 32 + lane] = h1[w];
            }
        }
    }
#pragma unroll
    for (int w = 0; w < PW; w++) if (valid[w]) {
        g_path_state[(p0 + w) * D + lane]      = h0[w];
        g_path_state[(p0 + w) * D + 32 + lane] = h1[w];
    }
}

// ---------------- link aggregation + link GRU (one step) ----------------
__global__ void k_link_gru(const int* __restrict__ p2l,
                           const float* __restrict__ wx, const float* __restrict__ wh,
                           const float* __restrict__ bx, const float* __restrict__ bh) {
    extern __shared__ float sm[];
    float* s_wx = sm;
    float* s_wh = sm + D * 3 * D;
    float* s_bx = sm + 2 * D * 3 * D;
    float* s_bh = s_bx + 3 * D;
    for (int i = threadIdx.x; i < D * 3 * D; i += blockDim.x) { s_wx[i] = wx[i]; s_wh[i] = wh[i]; }
    for (int i = threadIdx.x; i < 3 * D; i += blockDim.x) { s_bx[i] = bx[i]; s_bh[i] = bh[i]; }
    __syncthreads();

    int gw = (blockIdx.x * blockDim.x + threadIdx.x) >> 5;
    int lane = threadIdx.x & 31;
    if (gw >= NL) return;
    int l = gw;

    // path_sum = sum over DEG gathers from the sequence tensor
    float x0 = 0.f, x1 = 0.f;
    for (int d = 0; d < DEG; d++) {
        int pp = p2l[(l * DEG + d) * 2];
        int tt = p2l[(l * DEG + d) * 2 + 1];
        size_t base = ((size_t)pp * 9 + tt) * D;
        x0 += g_seq[base + lane];
        x1 += g_seq[base + 32 + lane];
    }
    float h0 = g_link_state[l * D + lane];
    float h1 = g_link_state[l * D + 32 + lane];

    float mx[6], mh[6];
#pragma unroll
    for (int m = 0; m < 6; m++) { mx[m] = s_bx[m * 32 + lane]; mh[m] = s_bh[m * 32 + lane]; }
#pragma unroll 16
    for (int k = 0; k < D; k++) {
        float xk = __shfl_sync(0xffffffffu, (k < 32) ? x0 : x1, k & 31);
        float hk = __shfl_sync(0xffffffffu, (k < 32) ? h0 : h1, k & 31);
#pragma unroll
        for (int m = 0; m < 6; m++) {
            mx[m] += xk * s_wx[k * 192 + m * 32 + lane];
            mh[m] += hk * s_wh[k * 192 + m * 32 + lane];
        }
    }
    float z0 = sigmoidf_(mx[0] + mh[0]);
    float z1 = sigmoidf_(mx[1] + mh[1]);
    float r0 = sigmoidf_(mx[2] + mh[2]);
    float r1 = sigmoidf_(mx[3] + mh[3]);
    float hh0 = tanhf(mx[4] + r0 * mh[4]);
    float hh1 = tanhf(mx[5] + r1 * mh[5]);
    g_link_state[l * D + lane]      = z0 * h0 + (1.f - z0) * hh0;
    g_link_state[l * D + 32 + lane] = z1 * h1 + (1.f - z1) * hh1;
}

// ---------------- readout MLP + delay reduction ----------------
__global__ void k_readout(const int* __restrict__ l2p, const float* __restrict__ cap,
                          const float* __restrict__ w1, const float* __restrict__ b1,
                          const float* __restrict__ w2, const float* __restrict__ b2,
                          const float* __restrict__ w3, const float* __restrict__ b3,
                          float* __restrict__ out) {
    __shared__ float s_w1[D * 32], s_b1[32], s_w2[32 * 16], s_b2[16], s_w3[16];
    for (int i = threadIdx.x; i < D * 32; i += blockDim.x) s_w1[i] = w1[i];
    for (int i = threadIdx.x; i < 32 * 16; i += blockDim.x) s_w2[i] = w2[i];
    if (threadIdx.x < 32) s_b1[threadIdx.x] = b1[threadIdx.x];
    if (threadIdx.x < 16) { s_b2[threadIdx.x] = b2[threadIdx.x]; s_w3[threadIdx.x] = w3[threadIdx.x]; }
    __syncthreads();
    int gw = (blockIdx.x * blockDim.x + threadIdx.x) >> 5;
    int lane = threadIdx.x & 31;
    if (gw >= NP) return;
    int p = gw;
    float bias3 = b3[0];
    float delay = 0.f;
    for (int t = 1; t <= LL; t++) {
        float h0 = g_seq[((size_t)p * 9 + t) * D + lane];
        float h1 = g_seq[((size_t)p * 9 + t) * D + 32 + lane];
        float acc = s_b1[lane];
#pragma unroll
        for (int k = 0; k < D; k++) {
            float hk = (k < 32) ? __shfl_sync(0xffffffffu, h0, k) : __shfl_sync(0xffffffffu, h1, k - 32);
            acc += hk * s_w1[k * 32 + lane];
        }
        float h1v = fmaxf(0.f, acc);
        float acc2 = (lane < 16) ? s_b2[lane] : 0.f;
#pragma unroll
        for (int k = 0; k < 32; k++) {
            float hk = __shfl_sync(0xffffffffu, h1v, k);
            if (lane < 16) acc2 += hk * s_w2[k * 16 + lane];
        }
        float contrib = (lane < 16) ? fmaxf(0.f, acc2) * s_w3[lane] : 0.f;
#pragma unroll
        for (int off = 16; off; off >>= 1) contrib += __shfl_xor_sync(0xffffffffu, contrib, off);
        if (lane == 0) {
            float o = contrib + bias3;
            // stable softplus = logaddexp(o, 0)
            float sp = fmaxf(o, 0.f) + log1pf(expf(-fabsf(o)));
            int li = l2p[p * LL + (t - 1)];
            delay += sp / cap[li];
        }
    }
    if (lane == 0) out[p] = delay;
}

// ---------------- launch ----------------
extern "C" void kernel_launch(void* const* d_in, const int* in_sizes, int n_in,
                              void* d_out, int out_size) {
    const float* ft    = (const float*)d_in[0];
    const float* fpk   = (const float*)d_in[1];
    const float* fps   = (const float*)d_in[2];
    const float* cap   = (const float*)d_in[3];
    const int*   l2p   = (const int*)d_in[4];
    const int*   p2l   = (const int*)d_in[5];
    const float* pe_w1 = (const float*)d_in[6];
    const float* pe_b1 = (const float*)d_in[7];
    const float* pe_w2 = (const float*)d_in[8];
    const float* pe_b2 = (const float*)d_in[9];
    const float* le_w1 = (const float*)d_in[10];
    const float* le_b1 = (const float*)d_in[11];
    const float* le_w2 = (const float*)d_in[12];
    const float* le_b2 = (const float*)d_in[13];
    const float* pg_wx = (const float*)d_in[14];
    const float* pg_wh = (const float*)d_in[15];
    const float* pg_bx = (const float*)d_in[16];
    const float* pg_bh = (const float*)d_in[17];
    const float* lg_wx = (const float*)d_in[18];
    const float* lg_wh = (const float*)d_in[19];
    const float* lg_bx = (const float*)d_in[20];
    const float* lg_bh = (const float*)d_in[21];
    const float* ro_w1 = (const float*)d_in[22];
    const float* ro_b1 = (const float*)d_in[23];
    const float* ro_w2 = (const float*)d_in[24];
    const float* ro_b2 = (const float*)d_in[25];
    const float* ro_w3 = (const float*)d_in[26];
    const float* ro_b3 = (const float*)d_in[27];
    float* out = (float*)d_out;

    size_t smem_gru = (size_t)(2 * D * 3 * D + 2 * 3 * D) * sizeof(float); // 99840 B
    cudaFuncSetAttribute(k_path_gru, cudaFuncAttributeMaxDynamicSharedMemorySize, (int)smem_gru);
    cudaFuncSetAttribute(k_link_gru, cudaFuncAttributeMaxDynamicSharedMemorySize, (int)smem_gru);

    k_path_embed<<<(NP + 7) / 8, 256>>>(ft, fpk, fps, pe_w1, pe_b1, pe_w2, pe_b2);
    k_link_embed<<<(NL + 7) / 8, 256>>>(ft, cap, p2l, le_w1, le_b1, le_w2, le_b2);

    int n_groups = (NP + PW - 1) / PW;          // 12500 warps
    int gru_blocks = (n_groups + 7) / 8;        // 8 warps per block
    for (int it = 0; it < ITERS; it++) {
        k_path_gru<<<gru_blocks, 256, smem_gru>>>(l2p, pg_wx, pg_wh, pg_bx, pg_bh);
        k_link_gru<<<(NL + 7) / 8, 256, smem_gru>>>(p2l, lg_wx, lg_wh, lg_bx, lg_bh);
    }
    k_readout<<<(NP + 7) / 8, 256>>>(l2p, cap, ro_w1, ro_b1, ro_w2, ro_b2, ro_w3, ro_b3, out);
}

// round 2
// speedup vs baseline: 1.7526x; 1.7526x over previous
#include <cuda_runtime.h>
#include <math.h>

#define NP 50000
#define NL 10000
#define LL 8
#define DEG 40
#define D 64
#define ITERS 8
#define PWP 8   // paths per warp in the path-GRU kernel
#define PWL 4   // links per warp in the link-GRU kernel

// ---------------- device scratch ----------------
__device__ float g_path_state[NP * D];                 // 12.8 MB
__device__ float g_seq[(size_t)NP * 9 * D];            // 115.2 MB
__device__ float g_link_state[NL * D];                 // 2.56 MB
__device__ float g_link_mx[NL * 3 * D];                // 7.68 MB : link_state @ Wx + bx
__device__ float g_xsum[NL * D];                       // 2.56 MB : gathered path sums

// ---------------- helpers ----------------
__device__ __forceinline__ float sigm_(float x) {
    return __fdividef(1.f, 1.f + __expf(-x));
}
__device__ __forceinline__ float tanh_(float x) {
    float t = __expf(-2.f * fabsf(x));
    float r = __fdividef(1.f - t, 1.f + t);
    return copysignf(r, x);
}
__device__ __forceinline__ unsigned long long pack2(float a, float b) {
    unsigned long long d;
    asm("mov.b64 %0, {%1, %2};" : "=l"(d) : "f"(a), "f"(b));
    return d;
}
__device__ __forceinline__ float2 unpack2(unsigned long long v) {
    float2 r;
    asm("mov.b64 {%0, %1}, %2;" : "=f"(r.x), "=f"(r.y) : "l"(v));
    return r;
}
__device__ __forceinline__ unsigned long long fma2(unsigned long long a, unsigned long long b, unsigned long long c) {
    unsigned long long d;
    asm("fma.rn.f32x2 %0, %1, %2, %3;" : "=l"(d) : "l"(a), "l"(b), "l"(c));
    return d;
}

// ---------------- path embedding ----------------
__global__ void k_path_embed(const float* __restrict__ ft, const float* __restrict__ fp,
                             const float* __restrict__ fps,
                             const float* __restrict__ w1, const float* __restrict__ b1,
                             const float* __restrict__ w2, const float* __restrict__ b2) {
    __shared__ float s_w1[3 * D], s_w2[D * D], s_b1[D], s_b2[D];
    for (int i = threadIdx.x; i < 3 * D; i += blockDim.x) s_w1[i] = w1[i];
    for (int i = threadIdx.x; i < D * D; i += blockDim.x) s_w2[i] = w2[i];
    for (int i = threadIdx.x; i < D; i += blockDim.x) { s_b1[i] = b1[i]; s_b2[i] = b2[i]; }
    __syncthreads();
    int gw = (blockIdx.x * blockDim.x + threadIdx.x) >> 5;
    int lane = threadIdx.x & 31;
    if (gw >= NP) return;
    int p = gw;
    float i0 = ft[p] * 1e-4f;
    float i1 = fp[p] * 1e-3f;
    float i2 = fps[p] * 1e-3f;
    float h0 = fmaxf(0.f, i0 * s_w1[lane]      + i1 * s_w1[D + lane]      + i2 * s_w1[2 * D + lane]      + s_b1[lane]);
    float h1 = fmaxf(0.f, i0 * s_w1[32 + lane] + i1 * s_w1[D + 32 + lane] + i2 * s_w1[2 * D + 32 + lane] + s_b1[32 + lane]);
    float o0 = s_b2[lane], o1 = s_b2[32 + lane];
#pragma unroll
    for (int k = 0; k < D; k++) {
        float hk = (k < 32) ? __shfl_sync(0xffffffffu, h0, k) : __shfl_sync(0xffffffffu, h1, k - 32);
        o0 += hk * s_w2[k * D + lane];
        o1 += hk * s_w2[k * D + 32 + lane];
    }
    g_path_state[p * D + lane]      = fmaxf(0.f, o0);
    g_path_state[p * D + 32 + lane] = fmaxf(0.f, o1);
}

// ---------------- link embedding ----------------
__global__ void k_link_embed(const float* __restrict__ ft, const float* __restrict__ cap,
                             const int* __restrict__ p2l,
                             const float* __restrict__ w1, const float* __restrict__ b1,
                             const float* __restrict__ w2, const float* __restrict__ b2) {
    __shared__ float s_w1[2 * D], s_w2[D * D], s_b1[D], s_b2[D];
    for (int i = threadIdx.x; i < 2 * D; i += blockDim.x) s_w1[i] = w1[i];
    for (int i = threadIdx.x; i < D * D; i += blockDim.x) s_w2[i] = w2[i];
    for (int i = threadIdx.x; i < D; i += blockDim.x) { s_b1[i] = b1[i]; s_b2[i] = b2[i]; }
    __syncthreads();
    int gw = (blockIdx.x * blockDim.x + threadIdx.x) >> 5;
    int lane = threadIdx.x & 31;
    if (gw >= NL) return;
    int l = gw;
    float s = 0.f;
    for (int d = lane; d < DEG; d += 32) s += ft[p2l[(l * DEG + d) * 2]];
#pragma unroll
    for (int off = 16; off; off >>= 1) s += __shfl_xor_sync(0xffffffffu, s, off);
    float c = cap[l];
    float i0 = c * 1e-5f;
    float i1 = s / (c * 1e9f);
    float h0 = fmaxf(0.f, i0 * s_w1[lane]      + i1 * s_w1[D + lane]      + s_b1[lane]);
    float h1 = fmaxf(0.f, i0 * s_w1[32 + lane] + i1 * s_w1[D + 32 + lane] + s_b1[32 + lane]);
    float o0 = s_b2[lane], o1 = s_b2[32 + lane];
#pragma unroll
    for (int k = 0; k < D; k++) {
        float hk = (k < 32) ? __shfl_sync(0xffffffffu, h0, k) : __shfl_sync(0xffffffffu, h1, k - 32);
        o0 += hk * s_w2[k * D + lane];
        o1 += hk * s_w2[k * D + 32 + lane];
    }
    g_link_state[l * D + lane]      = fmaxf(0.f, o0);
    g_link_state[l * D + 32 + lane] = fmaxf(0.f, o1);
}

// ---------------- link_mx = link_state @ Wx + bx (initial; later fused in link GRU) ----------------
__global__ void k_link_mx(const float* __restrict__ wx, const float* __restrict__ bx) {
    extern __shared__ float sm[];
    float* s_wx = sm;           // D*3D
    float* s_bx = sm + D * 3 * D;
    for (int i = threadIdx.x; i < D * 3 * D; i += blockDim.x) s_wx[i] = wx[i];
    for (int i = threadIdx.x; i < 3 * D; i += blockDim.x) s_bx[i] = bx[i];
    __syncthreads();
    int gw = (blockIdx.x * blockDim.x + threadIdx.x) >> 5;
    int lane = threadIdx.x & 31;
    if (gw >= NL) return;
    int l = gw;
    float h0 = g_link_state[l * D + lane];
    float h1 = g_link_state[l * D + 32 + lane];
    float acc[6];
#pragma unroll
    for (int m = 0; m < 6; m++) acc[m] = s_bx[m * 32 + lane];
#pragma unroll 8
    for (int k = 0; k < D; k++) {
        float hk = (k < 32) ? __shfl_sync(0xffffffffu, h0, k) : __shfl_sync(0xffffffffu, h1, k - 32);
#pragma unroll
        for (int m = 0; m < 6; m++) acc[m] += hk * s_wx[k * 192 + m * 32 + lane];
    }
#pragma unroll
    for (int m = 0; m < 6; m++) g_link_mx[l * 192 + m * 32 + lane] = acc[m];
}

// ---------------- path GRU: h-side only, packed f32x2, mx gathered ----------------
__global__ void __launch_bounds__(256, 2)
k_path_gru(const int* __restrict__ l2p,
           const float* __restrict__ wh, const float* __restrict__ bh) {
    extern __shared__ float sm[];
    float* s_wh2 = sm;                 // 64 * 384 : replicated pairs {w,w}
    float* s_bh  = sm + D * 384;       // 192
    for (int i = threadIdx.x; i < D * 192; i += blockDim.x) {
        float v = wh[i];
        s_wh2[2 * i] = v; s_wh2[2 * i + 1] = v;
    }
    for (int i = threadIdx.x; i < 192; i += blockDim.x) s_bh[i] = bh[i];
    __syncthreads();

    int gw = (blockIdx.x * blockDim.x + threadIdx.x) >> 5;
    int lane = threadIdx.x & 31;
    if (gw >= NP / PWP) return;   // 6250 warps exactly
    int p0 = gw * PWP;

    float h0[PWP], h1[PWP];
#pragma unroll
    for (int w = 0; w < PWP; w++) {
        h0[w] = g_path_state[(p0 + w) * D + lane];
        h1[w] = g_path_state[(p0 + w) * D + 32 + lane];
        float* sp = g_seq + ((size_t)(p0 + w) * 9) * D;
        sp[lane] = h0[w]; sp[32 + lane] = h1[w];
    }

    for (int t = 0; t < LL; t++) {
        unsigned long long acc[PWP / 2][6];
        float mxh[PWP][2];
#pragma unroll
        for (int wp = 0; wp < PWP / 2; wp++) {
            int pa = p0 + 2 * wp, pb = pa + 1;
            const float* ra = g_link_mx + (size_t)l2p[pa * LL + t] * 192;
            const float* rb = g_link_mx + (size_t)l2p[pb * LL + t] * 192;
#pragma unroll
            for (int m = 0; m < 4; m++) {
                float b = s_bh[m * 32 + lane];
                acc[wp][m] = pack2(b + ra[m * 32 + lane], b + rb[m * 32 + lane]);
            }
#pragma unroll
            for (int m = 4; m < 6; m++) {
                float b = s_bh[m * 32 + lane];
                acc[wp][m] = pack2(b, b);
                mxh[2 * wp][m - 4]     = ra[m * 32 + lane];
                mxh[2 * wp + 1][m - 4] = rb[m * 32 + lane];
            }
        }

#pragma unroll 8
        for (int k = 0; k < 32; k++) {
            const float* wk = s_wh2 + k * 384 + lane * 2;
            unsigned long long w2[6];
#pragma unroll
            for (int m = 0; m < 6; m++) w2[m] = *(const unsigned long long*)(wk + m * 64);
#pragma unroll
            for (int wp = 0; wp < PWP / 2; wp++) {
                float a = __shfl_sync(0xffffffffu, h0[2 * wp], k);
                float b = __shfl_sync(0xffffffffu, h0[2 * wp + 1], k);
                unsigned long long ab = pack2(a, b);
#pragma unroll
                for (int m = 0; m < 6; m++) acc[wp][m] = fma2(ab, w2[m], acc[wp][m]);
            }
        }
#pragma unroll 8
        for (int k = 0; k < 32; k++) {
            const float* wk = s_wh2 + (k + 32) * 384 + lane * 2;
            unsigned long long w2[6];
#pragma unroll
            for (int m = 0; m < 6; m++) w2[m] = *(const unsigned long long*)(wk + m * 64);
#pragma unroll
            for (int wp = 0; wp < PWP / 2; wp++) {
                float a = __shfl_sync(0xffffffffu, h1[2 * wp], k);
                float b = __shfl_sync(0xffffffffu, h1[2 * wp + 1], k);
                unsigned long long ab = pack2(a, b);
#pragma unroll
                for (int m = 0; m < 6; m++) acc[wp][m] = fma2(ab, w2[m], acc[wp][m]);
            }
        }

#pragma unroll
        for (int wp = 0; wp < PWP / 2; wp++) {
            float2 m0 = unpack2(acc[wp][0]);
            float2 m1 = unpack2(acc[wp][1]);
            float2 m2 = unpack2(acc[wp][2]);
            float2 m3 = unpack2(acc[wp][3]);
            float2 m4 = unpack2(acc[wp][4]);
            float2 m5 = unpack2(acc[wp][5]);
            {
                int w = 2 * wp;
                float z0 = sigm_(m0.x), z1 = sigm_(m1.x);
                float r0 = sigm_(m2.x), r1 = sigm_(m3.x);
                float hh0 = tanh_(mxh[w][0] + r0 * m4.x);
                float hh1 = tanh_(mxh[w][1] + r1 * m5.x);
                h0[w] = z0 * h0[w] + (1.f - z0) * hh0;
                h1[w] = z1 * h1[w] + (1.f - z1) * hh1;
                float* sp = g_seq + ((size_t)(p0 + w) * 9 + t + 1) * D;
                sp[lane] = h0[w]; sp[32 + lane] = h1[w];
            }
            {
                int w = 2 * wp + 1;
                float z0 = sigm_(m0.y), z1 = sigm_(m1.y);
                float r0 = sigm_(m2.y), r1 = sigm_(m3.y);
                float hh0 = tanh_(mxh[w][0] + r0 * m4.y);
                float hh1 = tanh_(mxh[w][1] + r1 * m5.y);
                h0[w] = z0 * h0[w] + (1.f - z0) * hh0;
                h1[w] = z1 * h1[w] + (1.f - z1) * hh1;
                float* sp = g_seq + ((size_t)(p0 + w) * 9 + t + 1) * D;
                sp[lane] = h0[w]; sp[32 + lane] = h1[w];
            }
        }
    }
#pragma unroll
    for (int w = 0; w < PWP; w++) {
        g_path_state[(p0 + w) * D + lane]      = h0[w];
        g_path_state[(p0 + w) * D + 32 + lane] = h1[w];
    }
}

// ---------------- gather: path_sum per link (high occupancy, no smem) ----------------
__global__ void k_gather(const int* __restrict__ p2l) {
    int gw = (blockIdx.x * blockDim.x + threadIdx.x) >> 5;
    int lane = threadIdx.x & 31;
    if (gw >= NL) return;
    int l = gw;
    const int2* e = (const int2*)p2l + (size_t)l * DEG;
    float x0 = 0.f, x1 = 0.f;
#pragma unroll
    for (int d = 0; d < DEG; d++) {
        int2 pt = __ldg(&e[d]);
        const float* sp = g_seq + ((size_t)pt.x * 9 + pt.y) * D;
        x0 += sp[lane];
        x1 += sp[32 + lane];
    }
    g_xsum[l * D + lane]      = x0;
    g_xsum[l * D + 32 + lane] = x1;
}

// ---------------- link GRU (+ produce next-iteration link_mx) ----------------
__global__ void k_link_gru(const float* __restrict__ wx, const float* __restrict__ wh,
                           const float* __restrict__ bx, const float* __restrict__ bh,
                           const float* __restrict__ wxp, const float* __restrict__ bxp) {
    extern __shared__ float sm[];
    float* s_wx  = sm;                       // D*3D (link Wx)
    float* s_wh  = sm + D * 192;             // D*3D (link Wh)
    float* s_wxp = sm + 2 * D * 192;         // D*3D (path Wx, for link_mx)
    float* s_bx  = sm + 3 * D * 192;         // 192
    float* s_bh  = s_bx + 192;               // 192
    float* s_bxp = s_bh + 192;               // 192
    for (int i = threadIdx.x; i < D * 192; i += blockDim.x) {
        s_wx[i] = wx[i]; s_wh[i] = wh[i]; s_wxp[i] = wxp[i];
    }
    for (int i = threadIdx.x; i < 192; i += blockDim.x) {
        s_bx[i] = bx[i]; s_bh[i] = bh[i]; s_bxp[i] = bxp[i];
    }
    __syncthreads();
    int gw = (blockIdx.x * blockDim.x + threadIdx.x) >> 5;
    int lane = threadIdx.x & 31;
    if (gw >= NL / PWL) return;   // 2500 warps exactly

    for (int i = 0; i < PWL; i++) {
        int l = gw * PWL + i;
        float x0 = g_xsum[l * D + lane];
        float x1 = g_xsum[l * D + 32 + lane];
        float h0 = g_link_state[l * D + lane];
        float h1 = g_link_state[l * D + 32 + lane];
        float mx[6], mh[6];
#pragma unroll
        for (int m = 0; m < 6; m++) { mx[m] = s_bx[m * 32 + lane]; mh[m] = s_bh[m * 32 + lane]; }
#pragma unroll 8
        for (int k = 0; k < D; k++) {
            float xk = __shfl_sync(0xffffffffu, (k < 32) ? x0 : x1, k & 31);
            float hk = __shfl_sync(0xffffffffu, (k < 32) ? h0 : h1, k & 31);
#pragma unroll
            for (int m = 0; m < 6; m++) {
                mx[m] += xk * s_wx[k * 192 + m * 32 + lane];
                mh[m] += hk * s_wh[k * 192 + m * 32 + lane];
            }
        }
        float z0 = sigm_(mx[0] + mh[0]);
        float z1 = sigm_(mx[1] + mh[1]);
        float r0 = sigm_(mx[2] + mh[2]);
        float r1 = sigm_(mx[3] + mh[3]);
        float hh0 = tanh_(mx[4] + r0 * mh[4]);
        float hh1 = tanh_(mx[5] + r1 * mh[5]);
        float n0 = z0 * h0 + (1.f - z0) * hh0;
        float n1 = z1 * h1 + (1.f - z1) * hh1;
        g_link_state[l * D + lane]      = n0;
        g_link_state[l * D + 32 + lane] = n1;

        // next-iteration link_mx = n @ Wxp + bxp
        float acc[6];
#pragma unroll
        for (int m = 0; m < 6; m++) acc[m] = s_bxp[m * 32 + lane];
#pragma unroll 8
        for (int k = 0; k < D; k++) {
            float hk = __shfl_sync(0xffffffffu, (k < 32) ? n0 : n1, k & 31);
#pragma unroll
            for (int m = 0; m < 6; m++) acc[m] += hk * s_wxp[k * 192 + m * 32 + lane];
        }
#pragma unroll
        for (int m = 0; m < 6; m++) g_link_mx[l * 192 + m * 32 + lane] = acc[m];
    }
}

// ---------------- readout ----------------
__global__ void k_readout(const int* __restrict__ l2p, const float* __restrict__ cap,
                          const float* __restrict__ w1, const float* __restrict__ b1,
                          const float* __restrict__ w2, const float* __restrict__ b2,
                          const float* __restrict__ w3, const float* __restrict__ b3,
                          float* __restrict__ out) {
    __shared__ float s_w1[D * 32], s_b1[32], s_w2[32 * 16], s_b2[16], s_w3[16];
    for (int i = threadIdx.x; i < D * 32; i += blockDim.x) s_w1[i] = w1[i];
    for (int i = threadIdx.x; i < 32 * 16; i += blockDim.x) s_w2[i] = w2[i];
    if (threadIdx.x < 32) s_b1[threadIdx.x] = b1[threadIdx.x];
    if (threadIdx.x < 16) { s_b2[threadIdx.x] = b2[threadIdx.x]; s_w3[threadIdx.x] = w3[threadIdx.x]; }
    __syncthreads();
    int gw = (blockIdx.x * blockDim.x + threadIdx.x) >> 5;
    int lane = threadIdx.x & 31;
    if (gw >= NP) return;
    int p = gw;
    float bias3 = b3[0];
    float delay = 0.f;
    for (int t = 1; t <= LL; t++) {
        float h0 = g_seq[((size_t)p * 9 + t) * D + lane];
        float h1 = g_seq[((size_t)p * 9 + t) * D + 32 + lane];
        float acc = s_b1[lane];
#pragma unroll
        for (int k = 0; k < D; k++) {
            float hk = (k < 32) ? __shfl_sync(0xffffffffu, h0, k) : __shfl_sync(0xffffffffu, h1, k - 32);
            acc += hk * s_w1[k * 32 + lane];
        }
        float h1v = fmaxf(0.f, acc);
        float acc2 = (lane < 16) ? s_b2[lane] : 0.f;
#pragma unroll
        for (int k = 0; k < 32; k++) {
            float hk = __shfl_sync(0xffffffffu, h1v, k);
            if (lane < 16) acc2 += hk * s_w2[k * 16 + lane];
        }
        float contrib = (lane < 16) ? fmaxf(0.f, acc2) * s_w3[lane] : 0.f;
#pragma unroll
        for (int off = 16; off; off >>= 1) contrib += __shfl_xor_sync(0xffffffffu, contrib, off);
        if (lane == 0) {
            float o = contrib + bias3;
            float sp = fmaxf(o, 0.f) + log1pf(expf(-fabsf(o)));
            int li = l2p[p * LL + (t - 1)];
            delay += sp / cap[li];
        }
    }
    if (lane == 0) out[p] = delay;
}

// ---------------- launch ----------------
extern "C" void kernel_launch(void* const* d_in, const int* in_sizes, int n_in,
                              void* d_out, int out_size) {
    const float* ft    = (const float*)d_in[0];
    const float* fpk   = (const float*)d_in[1];
    const float* fps   = (const float*)d_in[2];
    const float* cap   = (const float*)d_in[3];
    const int*   l2p   = (const int*)d_in[4];
    const int*   p2l   = (const int*)d_in[5];
    const float* pe_w1 = (const float*)d_in[6];
    const float* pe_b1 = (const float*)d_in[7];
    const float* pe_w2 = (const float*)d_in[8];
    const float* pe_b2 = (const float*)d_in[9];
    const float* le_w1 = (const float*)d_in[10];
    const float* le_b1 = (const float*)d_in[11];
    const float* le_w2 = (const float*)d_in[12];
    const float* le_b2 = (const float*)d_in[13];
    const float* pg_wx = (const float*)d_in[14];
    const float* pg_wh = (const float*)d_in[15];
    const float* pg_bx = (const float*)d_in[16];
    const float* pg_bh = (const float*)d_in[17];
    const float* lg_wx = (const float*)d_in[18];
    const float* lg_wh = (const float*)d_in[19];
    const float* lg_bx = (const float*)d_in[20];
    const float* lg_bh = (const float*)d_in[21];
    const float* ro_w1 = (const float*)d_in[22];
    const float* ro_b1 = (const float*)d_in[23];
    const float* ro_w2 = (const float*)d_in[24];
    const float* ro_b2 = (const float*)d_in[25];
    const float* ro_w3 = (const float*)d_in[26];
    const float* ro_b3 = (const float*)d_in[27];
    float* out = (float*)d_out;

    size_t smem_pg = (size_t)(D * 384 + 192) * sizeof(float);            // 99072 B
    size_t smem_lg = (size_t)(3 * D * 192 + 3 * 192) * sizeof(float);    // 149760 B
    size_t smem_mx = (size_t)(D * 192 + 192) * sizeof(float);            // 49920 B
    cudaFuncSetAttribute(k_path_gru, cudaFuncAttributeMaxDynamicSharedMemorySize, (int)smem_pg);
    cudaFuncSetAttribute(k_link_gru, cudaFuncAttributeMaxDynamicSharedMemorySize, (int)smem_lg);
    cudaFuncSetAttribute(k_link_mx,  cudaFuncAttributeMaxDynamicSharedMemorySize, (int)smem_mx);

    k_path_embed<<<(NP + 7) / 8, 256>>>(ft, fpk, fps, pe_w1, pe_b1, pe_w2, pe_b2);
    k_link_embed<<<(NL + 7) / 8, 256>>>(ft, cap, p2l, le_w1, le_b1, le_w2, le_b2);
    k_link_mx<<<(NL + 7) / 8, 256, smem_mx>>>(pg_wx, pg_bx);

    int pg_blocks = (NP / PWP + 7) / 8;   // 782
    int lg_blocks = (NL / PWL + 7) / 8;   // 313
    for (int it = 0; it < ITERS; it++) {
        k_path_gru<<<pg_blocks, 256, smem_pg>>>(l2p, pg_wh, pg_bh);
        k_gather<<<(NL + 7) / 8, 256>>>(p2l);
        k_link_gru<<<lg_blocks, 256, smem_lg>>>(lg_wx, lg_wh, lg_bx, lg_bh, pg_wx, pg_bx);
    }
    k_readout<<<(NP + 7) / 8, 256>>>(l2p, cap, ro_w1, ro_b1, ro_w2, ro_b2, ro_w3, ro_b3, out);
}